// round 14
// baseline (speedup 1.0000x reference)
#include <cuda_runtime.h>
#include <cstdint>

// ============================================================================
// Router gate: x [32768, 2048] f32, w [64, 2048] f32.
// logits = x @ w^T ; probs = softmax ; top-8 vals + indices.
// Out: [probs N*64 | top_vals N*8 | indices(float) N*8]
//
// mma m16n8k8 TF32, 2-way split (x=xh+xm, w=wh+wm):
//   xh*wh -> chunk accumulator (k64), rebased into a smem master via RN FADD
//   xh*wm + xm*wh -> separate small-magnitude register accumulator
// R14: B-fragment + x register double-buffer inside the chunk (MMAs never
//      wait on LDS); master accumulator moved to smem (k64 rebase) to pay
//      the register cost; 3-stage cp.async ring, stage issued post-barrier.
//      TB=64, 256 threads, 2 CTAs/SM.
// ============================================================================

#define D 2048
#define TB 64             // tokens per CTA
#define NCH 64            // k32 staging chunks (rebase every 2)
#define BSTEP 4096        // B frag bytes per step
#define BCHUNK 16384      // 4 steps
#define XSTRIDE 144       // bytes per x row: 36 floats (CF swizzle)
#define XCHUNK 9216       // 64 rows * 144
#define BRING (3 * BCHUNK)            // 49152
#define XBASE BRING
#define MSOFF (BRING + 3 * XCHUNK)    // 76800
#define SMEM_SZ (MSOFF + 16384)       // 93184 -> 2 CTAs/SM
#define EPI_STRIDE 68

// weights split into tf32 h/m, HMMA B-fragment order:
// [step(256)][tile(8)][lane(32)] x uint4(bh0, bh1, bm0, bm1)
__device__ __align__(16) unsigned char g_bfrag[256 * BSTEP];

static __device__ __forceinline__ uint32_t smem_u32(const void* p) {
    uint32_t a;
    asm("{ .reg .u64 t; cvta.to.shared.u64 t, %1; cvt.u32.u64 %0, t; }"
        : "=r"(a) : "l"(p));
    return a;
}
static __device__ __forceinline__ void split2(float v, uint32_t& h, uint32_t& m) {
    asm("cvt.rna.tf32.f32 %0, %1;" : "=r"(h) : "f"(v));
    float r = v - __uint_as_float(h);
    asm("cvt.rna.tf32.f32 %0, %1;" : "=r"(m) : "f"(r));
}

#define MMA(d, a, b0_, b1_) \
    asm volatile("mma.sync.aligned.m16n8k8.row.col.f32.tf32.tf32.f32 " \
        "{%0,%1,%2,%3}, {%4,%5,%6,%7}, {%8,%9}, {%0,%1,%2,%3};" \
        : "+f"((d)[0]), "+f"((d)[1]), "+f"((d)[2]), "+f"((d)[3]) \
        : "r"((a)[0]), "r"((a)[1]), "r"((a)[2]), "r"((a)[3]), "r"(b0_), "r"(b1_))
#define MMA_ZC(d, a, b0_, b1_) \
    asm volatile("mma.sync.aligned.m16n8k8.row.col.f32.tf32.tf32.f32 " \
        "{%0,%1,%2,%3}, {%4,%5,%6,%7}, {%8,%9}, {%10,%10,%10,%10};" \
        : "=f"((d)[0]), "=f"((d)[1]), "=f"((d)[2]), "=f"((d)[3]) \
        : "r"((a)[0]), "r"((a)[1]), "r"((a)[2]), "r"((a)[3]), "r"(b0_), "r"(b1_), \
          "f"(0.0f))

#define CP16(s, g) \
    asm volatile("cp.async.cg.shared.global [%0], [%1], 16;" :: "r"(s), "l"(g) : "memory")
#define CP_COMMIT() asm volatile("cp.async.commit_group;" ::: "memory")
#define CP_WAIT1()  asm volatile("cp.async.wait_group 1;" ::: "memory")
#define CP_WAIT0()  asm volatile("cp.async.wait_group 0;" ::: "memory")
#define LDS128(v, a) \
    asm volatile("ld.shared.v4.b32 {%0,%1,%2,%3}, [%4];" \
        : "=r"((v).x), "=r"((v).y), "=r"((v).z), "=r"((v).w) : "r"(a))
#define LDSF(v, a) \
    asm volatile("ld.shared.f32 %0, [%1];" : "=f"(v) : "r"(a))
#define STSF(a, v) \
    asm volatile("st.shared.f32 [%0], %1;" :: "r"(a), "f"(v) : "memory")

// ---------------- weight prep ----------------
__global__ void prep_bfrag(const float* __restrict__ w) {
    int i = blockIdx.x * blockDim.x + threadIdx.x;   // (step*8 + tile)*32 + lane
    if (i >= 256 * 8 * 32) return;
    int lane = i & 31;
    int tile = (i >> 5) & 7;
    int step = i >> 8;
    int e = tile * 8 + (lane >> 2);
    int tq = lane & 3;
    int k0 = step * 8;
    const float* wr = w + (size_t)e * D;
    uint32_t h0, m0, h1, m1;
    split2(wr[k0 + tq],     h0, m0);
    split2(wr[k0 + tq + 4], h1, m1);
    *reinterpret_cast<uint4*>(g_bfrag + step * BSTEP + tile * 512 + lane * 16) =
        make_uint4(h0, h1, m0, m1);
}

// stage chunk c into ring stage s (B 16KB + X 9KB), one commit group
static __device__ __forceinline__ void stage_chunk(uint32_t sbase,
                                                   const unsigned char* xg,
                                                   int c, int s, int tid) {
    const unsigned char* bsrc = g_bfrag + (size_t)c * BCHUNK;
    uint32_t bd = sbase + s * BCHUNK;
    uint32_t xd = sbase + XBASE + s * XCHUNK;
    size_t kb = (size_t)c * 128;   // 32 floats
    #pragma unroll
    for (int p = 0; p < 4; ++p) {              // 4 x 256 x 16B = 16KB exactly
        int u = tid + p * 256;
        CP16(bd + u * 16, bsrc + u * 16);
    }
    #pragma unroll
    for (int p = 0; p < 2; ++p) {              // 512 x 16B: 64 rows x 8 segs
        int u = tid + p * 256;
        int row = u >> 3, seg = u & 7;
        CP16(xd + row * XSTRIDE + seg * 16,
             xg + (size_t)row * (D * 4) + kb + seg * 16);
    }
    CP_COMMIT();
}

// ---------------- main fused kernel ----------------
__global__ void __launch_bounds__(256, 2)
moe_gate(const float* __restrict__ x, float* __restrict__ out, int Ntok) {
    extern __shared__ __align__(16) float smemf[];
    const uint32_t sbase = smem_u32(smemf);
    const int tid = threadIdx.x;
    const int wid = tid >> 5;
    const int lane = tid & 31;
    const int g = lane >> 2;
    const int t4 = lane & 3;
    const int tg = wid >> 1;          // token group 0..3 (16 tokens, m16)
    const int eh = wid & 1;           // expert half 0..1 (32 experts, n32)
    const size_t t0 = (size_t)blockIdx.x * TB;
    const unsigned char* xg = reinterpret_cast<const unsigned char*>(x + t0 * D);

    float chx[4][4], cc[4][4];
    #pragma unroll
    for (int i = 0; i < 4; ++i)
        #pragma unroll
        for (int j = 0; j < 4; ++j) cc[i][j] = 0.0f;

    // zero the smem master accumulator ([16][256] floats, lane-conflict-free)
    const uint32_t msb = sbase + MSOFF + tid * 4;
    #pragma unroll
    for (int j = 0; j < 16; ++j) STSF(msb + j * 1024, 0.0f);

    // prologue: stage chunks 0 and 1
    stage_chunk(sbase, xg, 0, 0, tid);
    stage_chunk(sbase, xg, 1, 1, tid);

    // x fragment gather offset: rows tg*16 + {g, g+8}
    const uint32_t xfrag = (tg * 16 + g) * XSTRIDE + t4 * 4;

    int st = 0;       // ch % 3
    int st2 = 2;      // (ch+2) % 3
    for (int ch = 0; ch < NCH; ++ch) {
        if (ch + 1 < NCH) CP_WAIT1(); else CP_WAIT0();
        __syncthreads();                         // chunk ch visible; stage st2 free
        if (ch + 2 < NCH) stage_chunk(sbase, xg, ch + 2, st2, tid);

        const uint32_t bstg = sbase + st * BCHUNK + eh * 2048 + lane * 16;
        const uint32_t xstg = sbase + XBASE + st * XCHUNK + xfrag;

        // preload step-0 operands
        uint4 b0, b1, b2, b3;
        LDS128(b0, bstg);
        LDS128(b1, bstg + 512);
        LDS128(b2, bstg + 1024);
        LDS128(b3, bstg + 1536);
        float x0, x1, x2, x3;
        LDSF(x0, xstg);
        LDSF(x1, xstg + 16);
        LDSF(x2, xstg + 8 * XSTRIDE);
        LDSF(x3, xstg + 8 * XSTRIDE + 16);

        #pragma unroll
        for (int s4 = 0; s4 < 4; ++s4) {
            // shadow loads for step s4+1 (off the MMA critical path)
            uint4 nb0, nb1, nb2, nb3;
            float nx0, nx1, nx2, nx3;
            if (s4 < 3) {
                const uint32_t bb = bstg + (s4 + 1) * BSTEP;
                LDS128(nb0, bb);
                LDS128(nb1, bb + 512);
                LDS128(nb2, bb + 1024);
                LDS128(nb3, bb + 1536);
                const uint32_t xp = xstg + (s4 + 1) * 32;
                LDSF(nx0, xp);
                LDSF(nx1, xp + 16);
                LDSF(nx2, xp + 8 * XSTRIDE);
                LDSF(nx3, xp + 8 * XSTRIDE + 16);
            }

            uint32_t Ah[4], Am[4];
            split2(x0, Ah[0], Am[0]);
            split2(x2, Ah[1], Am[1]);
            split2(x1, Ah[2], Am[2]);
            split2(x3, Ah[3], Am[3]);

            // corrections (Am x wh) first -- independent of chx
            MMA(cc[0], Am, b0.x, b0.y);
            MMA(cc[1], Am, b1.x, b1.y);
            MMA(cc[2], Am, b2.x, b2.y);
            MMA(cc[3], Am, b3.x, b3.y);
            // hh chunk terms: restart onto zero C at head of even chunk (k64)
            if (s4 == 0 && (ch & 1) == 0) {
                MMA_ZC(chx[0], Ah, b0.x, b0.y);
                MMA_ZC(chx[1], Ah, b1.x, b1.y);
                MMA_ZC(chx[2], Ah, b2.x, b2.y);
                MMA_ZC(chx[3], Ah, b3.x, b3.y);
            } else {
                MMA(chx[0], Ah, b0.x, b0.y);
                MMA(chx[1], Ah, b1.x, b1.y);
                MMA(chx[2], Ah, b2.x, b2.y);
                MMA(chx[3], Ah, b3.x, b3.y);
            }
            // corrections (Ah x wm) -- dependent pairs 8 MMAs apart
            MMA(cc[0], Ah, b0.z, b0.w);
            MMA(cc[1], Ah, b1.z, b1.w);
            MMA(cc[2], Ah, b2.z, b2.w);
            MMA(cc[3], Ah, b3.z, b3.w);

            b0 = nb0; b1 = nb1; b2 = nb2; b3 = nb3;
            x0 = nx0; x1 = nx1; x2 = nx2; x3 = nx3;
        }

        // rebase every k64 (odd chunk): master(smem) += chunk (RN fp32)
        if (ch & 1) {
            #pragma unroll
            for (int i = 0; i < 4; ++i)
                #pragma unroll
                for (int j = 0; j < 4; ++j) {
                    uint32_t a = msb + (i * 4 + j) * 1024;
                    float v;
                    LDSF(v, a);
                    v += chx[i][j];
                    STSF(a, v);
                }
        }

        st = (st == 2) ? 0 : st + 1;
        st2 = (st2 == 2) ? 0 : st2 + 1;
    }
    __syncthreads();   // all compute done before epilogue smem reuse

    // -------- epilogue: logits -> smem, thread-per-token softmax + top-8 ----
    float msv[16];
    #pragma unroll
    for (int j = 0; j < 16; ++j) LDSF(msv[j], msb + j * 1024);

    float* L = smemf;   // [64][EPI_STRIDE]
    {
        int r0 = tg * 16 + g;
        #pragma unroll
        for (int j = 0; j < 4; ++j) {
            int n0 = eh * 32 + j * 8 + 2 * t4;
            *reinterpret_cast<float2*>(L + r0 * EPI_STRIDE + n0) =
                make_float2(msv[j * 4 + 0] + cc[j][0], msv[j * 4 + 1] + cc[j][1]);
            *reinterpret_cast<float2*>(L + (r0 + 8) * EPI_STRIDE + n0) =
                make_float2(msv[j * 4 + 2] + cc[j][2], msv[j * 4 + 3] + cc[j][3]);
        }
    }
    __syncthreads();

    if (tid < TB) {
        float pv[64];
        const float* Lr = L + tid * EPI_STRIDE;
        #pragma unroll
        for (int c = 0; c < 16; ++c) {
            float4 v = *reinterpret_cast<const float4*>(Lr + 4 * c);
            pv[4 * c] = v.x; pv[4 * c + 1] = v.y;
            pv[4 * c + 2] = v.z; pv[4 * c + 3] = v.w;
        }
        float mx = pv[0];
        #pragma unroll
        for (int c = 1; c < 64; ++c) mx = fmaxf(mx, pv[c]);
        float s = 0.0f;
        #pragma unroll
        for (int c = 0; c < 64; ++c) { pv[c] = __expf(pv[c] - mx); s += pv[c]; }
        float inv = 1.0f / s;
        #pragma unroll
        for (int c = 0; c < 64; ++c) pv[c] *= inv;

        const size_t gt = t0 + tid;
        float* pr = out + gt * 64;
        #pragma unroll
        for (int c = 0; c < 16; ++c)
            *reinterpret_cast<float4*>(pr + 4 * c) =
                make_float4(pv[4 * c], pv[4 * c + 1], pv[4 * c + 2], pv[4 * c + 3]);

        // top-8 insertion; strict '>' keeps smaller index on ties (lax.top_k)
        float tv[8]; int ti[8];
        #pragma unroll
        for (int r = 0; r < 8; ++r) { tv[r] = -1.0f; ti[r] = 0; }
        #pragma unroll
        for (int j = 0; j < 64; ++j) {
            float v = pv[j];
            if (v > tv[7]) {
                tv[7] = v; ti[7] = j;
                #pragma unroll
                for (int q = 7; q > 0; --q) {
                    bool sw = tv[q] > tv[q - 1];
                    float fv = sw ? tv[q - 1] : tv[q];
                    int   fi = sw ? ti[q - 1] : ti[q];
                    tv[q - 1] = sw ? tv[q] : tv[q - 1];
                    ti[q - 1] = sw ? ti[q] : ti[q - 1];
                    tv[q] = fv; ti[q] = fi;
                }
            }
        }
        const size_t tvo = (size_t)Ntok * 64;
        const size_t ixo = tvo + (size_t)Ntok * 8;
        *reinterpret_cast<float4*>(out + tvo + gt * 8)     =
            make_float4(tv[0], tv[1], tv[2], tv[3]);
        *reinterpret_cast<float4*>(out + tvo + gt * 8 + 4) =
            make_float4(tv[4], tv[5], tv[6], tv[7]);
        *reinterpret_cast<float4*>(out + ixo + gt * 8)     =
            make_float4((float)ti[0], (float)ti[1], (float)ti[2], (float)ti[3]);
        *reinterpret_cast<float4*>(out + ixo + gt * 8 + 4) =
            make_float4((float)ti[4], (float)ti[5], (float)ti[6], (float)ti[7]);
    }
}

extern "C" void kernel_launch(void* const* d_in, const int* in_sizes, int n_in,
                              void* d_out, int out_size) {
    const float* x = (const float*)d_in[0];
    const float* w = (const float*)d_in[1];
    float* out = (float*)d_out;
    int Ntok = in_sizes[0] / D;     // 32768

    cudaFuncSetAttribute(moe_gate, cudaFuncAttributeMaxDynamicSharedMemorySize, SMEM_SZ);
    prep_bfrag<<<(256 * 8 * 32 + 255) / 256, 256>>>(w);
    moe_gate<<<Ntok / TB, 256, SMEM_SZ>>>(x, out, Ntok);
}

// round 16
// speedup vs baseline: 1.5987x; 1.5987x over previous
#include <cuda_runtime.h>
#include <cuda_fp16.h>
#include <cstdint>

// ============================================================================
// Router gate: x [32768, 2048] f32, w [64, 2048] f32.
// logits = x @ w^T ; probs = softmax ; top-8 vals + indices.
// Out: [probs N*64 | top_vals N*8 | indices(float) N*8]
//
// R16 = R15 with the cp.async alignment bug fixed (XSTRIDE 276 -> 272).
// fp16 m16n8k16 MMA (2x MACs/instr vs tf32 k8 -> half the HMMA count).
//   2-way split: x = xh+xm, w' = 256*w = wh+wm  (fp16 each; x256 keeps w
//   splits out of fp16 subnormals; epilogue multiplies by exact 2^-8).
//   xh*wh -> chunk accumulator (k64 = 4 chained MMAs), rebased into master
//            via RN FADD (kills tensor-core RZ accumulation bias)
//   xh*wm + xm*wh -> separate small-magnitude accumulator
//   TB=64, 256 threads, 2 CTAs/SM, 3-stage cp.async ring (post-barrier issue).
// ============================================================================

#define D 2048
#define TB 64             // tokens per CTA
#define NCH 32            // k64 chunks
#define BSTEP 4096        // B frag bytes per k16 step
#define BCHUNK 16384      // 4 steps = k64
#define XSTRIDE 272       // bytes per x row: 68 floats (16B-aligned, ~CF)
#define XCH 17408         // 64 rows * 272
#define XBASE (3 * BCHUNK)            // 49152
#define SMEM_SZ (XBASE + 3 * XCH)     // 101376 -> 2 CTAs/SM
#define EPI_STRIDE 68
#define OSCALE 0.00390625f            // 2^-8, exact

// weights scaled x256, split into fp16 h/m, HMMA B-fragment order:
// [step(128)][tile(8)][lane(32)] x uint4(bh_klo, bh_khi, bm_klo, bm_khi)
__device__ __align__(16) unsigned char g_bfrag[128 * BSTEP];

static __device__ __forceinline__ uint32_t smem_u32(const void* p) {
    uint32_t a;
    asm("{ .reg .u64 t; cvta.to.shared.u64 t, %1; cvt.u32.u64 %0, t; }"
        : "=r"(a) : "l"(p));
    return a;
}
// split a float pair into fp16 hi + fp16 residual, packed f16x2
static __device__ __forceinline__ void splitp(float a, float b,
                                              uint32_t& h, uint32_t& m) {
    __half2 h2 = __floats2half2_rn(a, b);
    float2 hf = __half22float2(h2);
    __half2 m2 = __floats2half2_rn(a - hf.x, b - hf.y);
    h = *reinterpret_cast<uint32_t*>(&h2);
    m = *reinterpret_cast<uint32_t*>(&m2);
}

#define MMA(d, a, b0_, b1_) \
    asm volatile("mma.sync.aligned.m16n8k16.row.col.f32.f16.f16.f32 " \
        "{%0,%1,%2,%3}, {%4,%5,%6,%7}, {%8,%9}, {%0,%1,%2,%3};" \
        : "+f"((d)[0]), "+f"((d)[1]), "+f"((d)[2]), "+f"((d)[3]) \
        : "r"((a)[0]), "r"((a)[1]), "r"((a)[2]), "r"((a)[3]), "r"(b0_), "r"(b1_))
#define MMA_ZC(d, a, b0_, b1_) \
    asm volatile("mma.sync.aligned.m16n8k16.row.col.f32.f16.f16.f32 " \
        "{%0,%1,%2,%3}, {%4,%5,%6,%7}, {%8,%9}, {%10,%10,%10,%10};" \
        : "=f"((d)[0]), "=f"((d)[1]), "=f"((d)[2]), "=f"((d)[3]) \
        : "r"((a)[0]), "r"((a)[1]), "r"((a)[2]), "r"((a)[3]), "r"(b0_), "r"(b1_), \
          "f"(0.0f))

#define CP16(s, g) \
    asm volatile("cp.async.cg.shared.global [%0], [%1], 16;" :: "r"(s), "l"(g) : "memory")
#define CP_COMMIT() asm volatile("cp.async.commit_group;" ::: "memory")
#define CP_WAIT1()  asm volatile("cp.async.wait_group 1;" ::: "memory")
#define CP_WAIT0()  asm volatile("cp.async.wait_group 0;" ::: "memory")
#define LDS128(v, a) \
    asm volatile("ld.shared.v4.b32 {%0,%1,%2,%3}, [%4];" \
        : "=r"((v).x), "=r"((v).y), "=r"((v).z), "=r"((v).w) : "r"(a))
#define LDSF2(u, v, a) \
    asm volatile("ld.shared.v2.f32 {%0,%1}, [%2];" : "=f"(u), "=f"(v) : "r"(a))

// ---------------- weight prep: scale x256, fp16 split, fragment pack -------
__global__ void prep_bfrag(const float* __restrict__ w) {
    int i = blockIdx.x * blockDim.x + threadIdx.x;   // (step*8 + tile)*32 + lane
    if (i >= 128 * 8 * 32) return;
    int lane = i & 31;
    int tile = (i >> 5) & 7;
    int step = i >> 8;
    int e = tile * 8 + (lane >> 2);
    int t4 = lane & 3;
    int k0 = step * 16 + 2 * t4;
    const float* wr = w + (size_t)e * D;
    uint32_t h0, m0, h1, m1;
    splitp(wr[k0] * 256.0f,     wr[k0 + 1] * 256.0f, h0, m0);   // k pair low
    splitp(wr[k0 + 8] * 256.0f, wr[k0 + 9] * 256.0f, h1, m1);   // k pair +8
    *reinterpret_cast<uint4*>(g_bfrag + step * BSTEP + tile * 512 + lane * 16) =
        make_uint4(h0, h1, m0, m1);
}

// stage chunk c (k64) into ring stage s (B 16KB + X 16KB), one commit group
static __device__ __forceinline__ void stage_chunk(uint32_t sbase,
                                                   const unsigned char* xg,
                                                   int c, int s, int tid) {
    const unsigned char* bsrc = g_bfrag + (size_t)c * BCHUNK;
    uint32_t bd = sbase + s * BCHUNK;
    uint32_t xd = sbase + XBASE + s * XCH;
    size_t kb = (size_t)c * 256;   // 64 floats
    #pragma unroll
    for (int p = 0; p < 4; ++p) {              // 4 x 256 x 16B = 16KB exactly
        int u = tid + p * 256;
        CP16(bd + u * 16, bsrc + u * 16);
    }
    #pragma unroll
    for (int p = 0; p < 4; ++p) {              // 1024 x 16B: 64 rows x 16 segs
        int u = tid + p * 256;
        int row = u >> 4, seg = u & 15;
        CP16(xd + row * XSTRIDE + seg * 16,
             xg + (size_t)row * (D * 4) + kb + seg * 16);
    }
    CP_COMMIT();
}

// ---------------- main fused kernel ----------------
__global__ void __launch_bounds__(256, 2)
moe_gate(const float* __restrict__ x, float* __restrict__ out, int Ntok) {
    extern __shared__ __align__(16) float smemf[];
    const uint32_t sbase = smem_u32(smemf);
    const int tid = threadIdx.x;
    const int wid = tid >> 5;
    const int lane = tid & 31;
    const int g = lane >> 2;
    const int t4 = lane & 3;
    const int tg = wid >> 1;          // token group 0..3 (16 tokens, m16)
    const int eh = wid & 1;           // expert half 0..1 (32 experts, n32)
    const size_t t0 = (size_t)blockIdx.x * TB;
    const unsigned char* xg = reinterpret_cast<const unsigned char*>(x + t0 * D);

    float chx[4][4], ms[4][4], cc[4][4];
    #pragma unroll
    for (int i = 0; i < 4; ++i)
        #pragma unroll
        for (int j = 0; j < 4; ++j) { ms[i][j] = 0.0f; cc[i][j] = 0.0f; }

    // prologue: stage chunks 0 and 1
    stage_chunk(sbase, xg, 0, 0, tid);
    stage_chunk(sbase, xg, 1, 1, tid);

    // x fragment gather offset: rows tg*16 + {g, g+8}, k pair at 2t4 (+8)
    const uint32_t xfrag = (tg * 16 + g) * XSTRIDE + t4 * 8;

    int st = 0;       // ch % 3
    for (int ch = 0; ch < NCH; ++ch) {
        if (ch + 1 < NCH) CP_WAIT1(); else CP_WAIT0();
        __syncthreads();                      // chunk ch visible; (ch+2)%3 free
        if (ch + 2 < NCH) stage_chunk(sbase, xg, ch + 2, (st + 2) % 3, tid);

        const uint32_t bstg = sbase + st * BCHUNK + eh * 2048 + lane * 16;
        const uint32_t xstg = sbase + XBASE + st * XCH + xfrag;

        // preload x for step 0
        float x0, x1, x2, x3, x4, x5, x6, x7;
        LDSF2(x0, x1, xstg);                          // row g,   k 2t4,2t4+1
        LDSF2(x2, x3, xstg + 32);                     // row g,   k +8
        LDSF2(x4, x5, xstg + 8 * XSTRIDE);            // row g+8, low
        LDSF2(x6, x7, xstg + 8 * XSTRIDE + 32);       // row g+8, +8

        #pragma unroll
        for (int s4 = 0; s4 < 4; ++s4) {
            // prefetch next step's x before the MMA burst
            float n0, n1, n2, n3, n4, n5, n6, n7;
            if (s4 < 3) {
                const uint32_t xp = xstg + (s4 + 1) * 64;
                LDSF2(n0, n1, xp);
                LDSF2(n2, n3, xp + 32);
                LDSF2(n4, n5, xp + 8 * XSTRIDE);
                LDSF2(n6, n7, xp + 8 * XSTRIDE + 32);
            }

            // A fragments m16n8k16: a0 = (g, klow pair), a1 = (g+8, klow),
            //                       a2 = (g, k+8 pair),  a3 = (g+8, k+8)
            uint32_t Ah[4], Am[4];
            splitp(x0, x1, Ah[0], Am[0]);
            splitp(x4, x5, Ah[1], Am[1]);
            splitp(x2, x3, Ah[2], Am[2]);
            splitp(x6, x7, Ah[3], Am[3]);

            const uint32_t bb = bstg + s4 * BSTEP;
            uint4 b0, b1, b2, b3;
            LDS128(b0, bb);
            LDS128(b1, bb + 512);
            LDS128(b2, bb + 1024);
            LDS128(b3, bb + 1536);

            // corrections (Am x wh) first -- independent of chx
            MMA(cc[0], Am, b0.x, b0.y);
            MMA(cc[1], Am, b1.x, b1.y);
            MMA(cc[2], Am, b2.x, b2.y);
            MMA(cc[3], Am, b3.x, b3.y);
            // hh chunk terms (restart onto zero C at chunk head)
            if (s4 == 0) {
                MMA_ZC(chx[0], Ah, b0.x, b0.y);
                MMA_ZC(chx[1], Ah, b1.x, b1.y);
                MMA_ZC(chx[2], Ah, b2.x, b2.y);
                MMA_ZC(chx[3], Ah, b3.x, b3.y);
            } else {
                MMA(chx[0], Ah, b0.x, b0.y);
                MMA(chx[1], Ah, b1.x, b1.y);
                MMA(chx[2], Ah, b2.x, b2.y);
                MMA(chx[3], Ah, b3.x, b3.y);
            }
            // corrections (Ah x wm) -- dependent pairs 8 MMAs apart
            MMA(cc[0], Ah, b0.z, b0.w);
            MMA(cc[1], Ah, b1.z, b1.w);
            MMA(cc[2], Ah, b2.z, b2.w);
            MMA(cc[3], Ah, b3.z, b3.w);

            x0 = n0; x1 = n1; x2 = n2; x3 = n3;
            x4 = n4; x5 = n5; x6 = n6; x7 = n7;
        }
        // rebase every k64 chunk: master += chunk (RN fp32, unbiased)
        #pragma unroll
        for (int i = 0; i < 4; ++i)
            #pragma unroll
            for (int j = 0; j < 4; ++j) ms[i][j] += chx[i][j];

        st = (st == 2) ? 0 : st + 1;
    }
    __syncthreads();   // all compute done before epilogue smem reuse

    // -------- epilogue: logits -> smem (x 2^-8), softmax + top-8 ------------
    float* L = smemf;   // [64][EPI_STRIDE]
    {
        int r0 = tg * 16 + g;
        #pragma unroll
        for (int j = 0; j < 4; ++j) {
            int n0 = eh * 32 + j * 8 + 2 * t4;
            *reinterpret_cast<float2*>(L + r0 * EPI_STRIDE + n0) =
                make_float2((ms[j][0] + cc[j][0]) * OSCALE,
                            (ms[j][1] + cc[j][1]) * OSCALE);
            *reinterpret_cast<float2*>(L + (r0 + 8) * EPI_STRIDE + n0) =
                make_float2((ms[j][2] + cc[j][2]) * OSCALE,
                            (ms[j][3] + cc[j][3]) * OSCALE);
        }
    }
    __syncthreads();

    if (tid < TB) {
        float pv[64];
        const float* Lr = L + tid * EPI_STRIDE;
        #pragma unroll
        for (int c = 0; c < 16; ++c) {
            float4 v = *reinterpret_cast<const float4*>(Lr + 4 * c);
            pv[4 * c] = v.x; pv[4 * c + 1] = v.y;
            pv[4 * c + 2] = v.z; pv[4 * c + 3] = v.w;
        }
        float mx = pv[0];
        #pragma unroll
        for (int c = 1; c < 64; ++c) mx = fmaxf(mx, pv[c]);
        float s = 0.0f;
        #pragma unroll
        for (int c = 0; c < 64; ++c) { pv[c] = __expf(pv[c] - mx); s += pv[c]; }
        float inv = 1.0f / s;
        #pragma unroll
        for (int c = 0; c < 64; ++c) pv[c] *= inv;

        const size_t gt = t0 + tid;
        float* pr = out + gt * 64;
        #pragma unroll
        for (int c = 0; c < 16; ++c)
            *reinterpret_cast<float4*>(pr + 4 * c) =
                make_float4(pv[4 * c], pv[4 * c + 1], pv[4 * c + 2], pv[4 * c + 3]);

        // top-8 insertion; strict '>' keeps smaller index on ties (lax.top_k)
        float tv[8]; int ti[8];
        #pragma unroll
        for (int r = 0; r < 8; ++r) { tv[r] = -1.0f; ti[r] = 0; }
        #pragma unroll
        for (int j = 0; j < 64; ++j) {
            float v = pv[j];
            if (v > tv[7]) {
                tv[7] = v; ti[7] = j;
                #pragma unroll
                for (int q = 7; q > 0; --q) {
                    bool sw = tv[q] > tv[q - 1];
                    float fv = sw ? tv[q - 1] : tv[q];
                    int   fi = sw ? ti[q - 1] : ti[q];
                    tv[q - 1] = sw ? tv[q] : tv[q - 1];
                    ti[q - 1] = sw ? ti[q] : ti[q - 1];
                    tv[q] = fv; ti[q] = fi;
                }
            }
        }
        const size_t tvo = (size_t)Ntok * 64;
        const size_t ixo = tvo + (size_t)Ntok * 8;
        *reinterpret_cast<float4*>(out + tvo + gt * 8)     =
            make_float4(tv[0], tv[1], tv[2], tv[3]);
        *reinterpret_cast<float4*>(out + tvo + gt * 8 + 4) =
            make_float4(tv[4], tv[5], tv[6], tv[7]);
        *reinterpret_cast<float4*>(out + ixo + gt * 8)     =
            make_float4((float)ti[0], (float)ti[1], (float)ti[2], (float)ti[3]);
        *reinterpret_cast<float4*>(out + ixo + gt * 8 + 4) =
            make_float4((float)ti[4], (float)ti[5], (float)ti[6], (float)ti[7]);
    }
}

extern "C" void kernel_launch(void* const* d_in, const int* in_sizes, int n_in,
                              void* d_out, int out_size) {
    const float* x = (const float*)d_in[0];
    const float* w = (const float*)d_in[1];
    float* out = (float*)d_out;
    int Ntok = in_sizes[0] / D;     // 32768

    cudaFuncSetAttribute(moe_gate, cudaFuncAttributeMaxDynamicSharedMemorySize, SMEM_SZ);
    prep_bfrag<<<(128 * 8 * 32 + 255) / 256, 256>>>(w);
    moe_gate<<<Ntok / TB, 256, SMEM_SZ>>>(x, out, Ntok);
}